// round 16
// baseline (speedup 1.0000x reference)
#include <cuda_runtime.h>
#include <cuda_bf16.h>
#include <cuda_fp16.h>
#include <cstdint>

#define BATCH 16
#define SEQ   2048
#define EMB   1024
#define DH    128

// q,k split-bf16, natural [b][s][d]: index 0=q, 1=k
static __device__ __align__(16) __nv_bfloat16 g_h[2][(size_t)BATCH * SEQ * DH];
static __device__ __align__(16) __nv_bfloat16 g_l[2][(size_t)BATCH * SEQ * DH];
// v single fp16, natural [b][s][d]
static __device__ __align__(16) __half g_vh[(size_t)BATCH * SEQ * DH];
// Split-bf16 weights for q,k, B-operand layout [which][n][k]
static __device__ __align__(16) __nv_bfloat16 g_whi[2][DH][EMB];
static __device__ __align__(16) __nv_bfloat16 g_wlo[2][DH][EMB];
// fp16 weight for v
static __device__ __align__(16) __half g_wvh[DH][EMB];

extern __shared__ char smdyn[];

// ---------------------------------------------------------------------------
__device__ __forceinline__ uint32_t smem_u32(const void* p) {
    uint32_t a;
    asm("{ .reg .u64 t; cvta.to.shared.u64 t, %1; cvt.u32.u64 %0, t; }"
        : "=r"(a) : "l"(p));
    return a;
}
__device__ __forceinline__ void ldsm4(uint32_t* r, uint32_t addr) {
    asm volatile("ldmatrix.sync.aligned.m8n8.x4.shared.b16 {%0,%1,%2,%3}, [%4];"
                 : "=r"(r[0]), "=r"(r[1]), "=r"(r[2]), "=r"(r[3]) : "r"(addr));
}
__device__ __forceinline__ void ldsm4t(uint32_t* r, uint32_t addr) {
    asm volatile("ldmatrix.sync.aligned.m8n8.x4.trans.shared.b16 {%0,%1,%2,%3}, [%4];"
                 : "=r"(r[0]), "=r"(r[1]), "=r"(r[2]), "=r"(r[3]) : "r"(addr));
}
__device__ __forceinline__ void mma_bf16(float* c, const uint32_t* a,
                                         uint32_t b0, uint32_t b1) {
    asm volatile(
        "mma.sync.aligned.m16n8k16.row.col.f32.bf16.bf16.f32 "
        "{%0,%1,%2,%3}, {%4,%5,%6,%7}, {%8,%9}, {%0,%1,%2,%3};"
        : "+f"(c[0]), "+f"(c[1]), "+f"(c[2]), "+f"(c[3])
        : "r"(a[0]), "r"(a[1]), "r"(a[2]), "r"(a[3]), "r"(b0), "r"(b1));
}
__device__ __forceinline__ void mma_f16(float* c, const uint32_t* a,
                                        uint32_t b0, uint32_t b1) {
    asm volatile(
        "mma.sync.aligned.m16n8k16.row.col.f32.f16.f16.f32 "
        "{%0,%1,%2,%3}, {%4,%5,%6,%7}, {%8,%9}, {%0,%1,%2,%3};"
        : "+f"(c[0]), "+f"(c[1]), "+f"(c[2]), "+f"(c[3])
        : "r"(a[0]), "r"(a[1]), "r"(a[2]), "r"(a[3]), "r"(b0), "r"(b1));
}
__device__ __forceinline__ uint32_t pk(__nv_bfloat16 a, __nv_bfloat16 b) {
    __nv_bfloat162 t = __halves2bfloat162(a, b);
    return *(uint32_t*)&t;
}
__device__ __forceinline__ uint32_t pkh(__half a, __half b) {
    __half2 t = __halves2half2(a, b);
    return *(uint32_t*)&t;
}
__device__ __forceinline__ uint32_t pkh2f(float a, float b) {
    uint32_t r;
    asm("cvt.rn.f16x2.f32 %0, %2, %1;" : "=r"(r) : "f"(a), "f"(b));
    return r;
}
__device__ __forceinline__ void cpa16(uint32_t dst, const void* src) {
    asm volatile("cp.async.cg.shared.global [%0], [%1], 16;"
                 :: "r"(dst), "l"(src) : "memory");
}
#define CP_COMMIT() asm volatile("cp.async.commit_group;" ::: "memory")
#define CP_WAIT0()  asm volatile("cp.async.wait_group 0;" ::: "memory")

__device__ __forceinline__ float fexp2(float x) {
    float r;
    asm("ex2.approx.f32 %0, %1;" : "=f"(r) : "f"(x));
    return r;
}

// log2(e) * 32 (score scale folded with exp->exp2 conversion)
#define SCL 46.166241308446828f

// ---------------------------------------------------------------------------
// Convert weights: q,k -> split bf16 [n][k]; v -> fp16 [n][k]
// ---------------------------------------------------------------------------
__global__ void wconv_kernel(const float* __restrict__ Wq,
                             const float* __restrict__ Wk,
                             const float* __restrict__ Wv)
{
    int idx = blockIdx.x * 256 + threadIdx.x;      // 0..393215
    int which = idx >> 17;
    int r = idx & 131071;                          // r = k*128 + n
    int n = r & 127;
    int k = r >> 7;
    const float* W = (which == 0) ? Wq : (which == 1) ? Wk : Wv;
    float x = W[r];
    if (which == 2) {
        g_wvh[n][k] = __float2half_rn(x);
    } else {
        __nv_bfloat16 hi = __float2bfloat16(x);
        __nv_bfloat16 lo = __float2bfloat16(x - __bfloat162float(hi));
        g_whi[which][n][k] = hi;
        g_wlo[which][n][k] = lo;
    }
}

// ---------------------------------------------------------------------------
// mma.sync projection (R15, unchanged). BK=64 double-buffered.
// ---------------------------------------------------------------------------
#define PJ_T      18432u
#define PJ_STAGE  (4u * PJ_T)
#define PJ_SMEM   (2u * PJ_STAGE) // 147456

__global__ __launch_bounds__(256)
void proj_mma_kernel(const float* __restrict__ X,
                     const float* __restrict__ bq,
                     const float* __restrict__ bk,
                     const float* __restrict__ bv)
{
    const uint32_t sb = smem_u32(smdyn);

    const int which = blockIdx.y;
    const bool isv  = (which == 2);
    const int m0    = blockIdx.x * 128;
    const int tid   = threadIdx.x;
    const int wid   = tid >> 5;
    const int lane  = tid & 31;
    const int warp_m = wid >> 1;
    const int warp_n = wid & 1;

    const __nv_bfloat16* __restrict__ whi =
        isv ? (const __nv_bfloat16*)&g_wvh[0][0] : &g_whi[which][0][0];
    const __nv_bfloat16* __restrict__ wlo =
        isv ? (const __nv_bfloat16*)&g_wvh[0][0] : &g_wlo[which][0][0];

    float c[2][8][4];
#pragma unroll
    for (int i = 0; i < 2; i++)
#pragma unroll
        for (int j = 0; j < 8; j++)
#pragma unroll
            for (int q = 0; q < 4; q++) c[i][j][q] = 0.f;

    const uint32_t a_off =
        (uint32_t)((warp_m * 32 + (lane & 15)) * 144 + (lane >> 4) * 16);
    const uint32_t b_off =
        (uint32_t)((warp_n * 64 + (lane & 7) + ((lane >> 4) << 3)) * 144 +
                   ((lane >> 3) & 1) * 16);

    float4 ra[8];

    auto cpasyncB = [&](uint32_t stage, int k0) {
#pragma unroll
        for (int i = 0; i < 4; i++) {
            int f = tid + i * 256;
            int n = f >> 3, k8 = f & 7;
            uint32_t off = (uint32_t)(n * 144 + k8 * 16);
            cpa16(stage + 2 * PJ_T + off, whi + (size_t)n * EMB + k0 + k8 * 8);
            if (!isv)
                cpa16(stage + 3 * PJ_T + off, wlo + (size_t)n * EMB + k0 + k8 * 8);
        }
    };
    auto loadA = [&](int k0) {
#pragma unroll
        for (int i = 0; i < 8; i++) {
            int f = tid + i * 256;
            int row = f >> 4, k4 = f & 15;
            ra[i] = *(const float4*)&X[(size_t)(m0 + row) * EMB + k0 + k4 * 4];
        }
    };
    auto storeA = [&](uint32_t stage) {
#pragma unroll
        for (int i = 0; i < 8; i++) {
            int f = tid + i * 256;
            int row = f >> 4, k4 = f & 15;
            float4 v = ra[i];
            uint32_t off = (uint32_t)(row * 144 + k4 * 8);
            if (isv) {
                uint64_t hv = (uint64_t)pkh(__float2half_rn(v.x), __float2half_rn(v.y))
                            | ((uint64_t)pkh(__float2half_rn(v.z), __float2half_rn(v.w)) << 32);
                asm volatile("st.shared.b64 [%0], %1;" :: "r"(stage + off), "l"(hv) : "memory");
            } else {
                __nv_bfloat16 h0 = __float2bfloat16(v.x);
                __nv_bfloat16 h1 = __float2bfloat16(v.y);
                __nv_bfloat16 h2 = __float2bfloat16(v.z);
                __nv_bfloat16 h3 = __float2bfloat16(v.w);
                __nv_bfloat16 l0 = __float2bfloat16(v.x - __bfloat162float(h0));
                __nv_bfloat16 l1 = __float2bfloat16(v.y - __bfloat162float(h1));
                __nv_bfloat16 l2 = __float2bfloat16(v.z - __bfloat162float(h2));
                __nv_bfloat16 l3 = __float2bfloat16(v.w - __bfloat162float(h3));
                uint64_t hv = (uint64_t)pk(h0, h1) | ((uint64_t)pk(h2, h3) << 32);
                uint64_t lv = (uint64_t)pk(l0, l1) | ((uint64_t)pk(l2, l3) << 32);
                asm volatile("st.shared.b64 [%0], %1;" :: "r"(stage + off), "l"(hv) : "memory");
                asm volatile("st.shared.b64 [%0], %1;" :: "r"(stage + PJ_T + off), "l"(lv) : "memory");
            }
        }
    };

    cpasyncB(sb, 0);
    CP_COMMIT();
    loadA(0);
    storeA(sb);
    CP_WAIT0();
    __syncthreads();

    for (int cch = 0; cch < 16; cch++) {
        const uint32_t cur = sb + (uint32_t)(cch & 1) * PJ_STAGE;
        const uint32_t nxt = sb + (uint32_t)((cch + 1) & 1) * PJ_STAGE;

        if (cch < 15) {
            cpasyncB(nxt, (cch + 1) * 64);
            CP_COMMIT();
            loadA((cch + 1) * 64);
        }

#pragma unroll
        for (int ks = 0; ks < 4; ks++) {
            uint32_t ah[2][4], al[2][4], bh[4][4], bl[4][4];
#pragma unroll
            for (int im = 0; im < 2; im++) {
                ldsm4(ah[im], cur + a_off + im * 2304 + ks * 32);
                if (!isv) ldsm4(al[im], cur + PJ_T + a_off + im * 2304 + ks * 32);
            }
#pragma unroll
            for (int jn2 = 0; jn2 < 4; jn2++) {
                ldsm4(bh[jn2], cur + 2 * PJ_T + b_off + jn2 * 2304 + ks * 32);
                if (!isv) ldsm4(bl[jn2], cur + 3 * PJ_T + b_off + jn2 * 2304 + ks * 32);
            }
            if (isv) {
#pragma unroll
                for (int im = 0; im < 2; im++)
#pragma unroll
                    for (int jn2 = 0; jn2 < 4; jn2++) {
                        mma_f16(c[im][jn2 * 2 + 0], ah[im], bh[jn2][0], bh[jn2][1]);
                        mma_f16(c[im][jn2 * 2 + 1], ah[im], bh[jn2][2], bh[jn2][3]);
                    }
            } else {
#pragma unroll
                for (int im = 0; im < 2; im++)
#pragma unroll
                    for (int jn2 = 0; jn2 < 4; jn2++) {
                        mma_bf16(c[im][jn2 * 2 + 0], ah[im], bh[jn2][0], bh[jn2][1]);
                        mma_bf16(c[im][jn2 * 2 + 1], ah[im], bh[jn2][2], bh[jn2][3]);
                        mma_bf16(c[im][jn2 * 2 + 0], ah[im], bl[jn2][0], bl[jn2][1]);
                        mma_bf16(c[im][jn2 * 2 + 1], ah[im], bl[jn2][2], bl[jn2][3]);
                        mma_bf16(c[im][jn2 * 2 + 0], al[im], bh[jn2][0], bh[jn2][1]);
                        mma_bf16(c[im][jn2 * 2 + 1], al[im], bh[jn2][2], bh[jn2][3]);
                    }
            }
        }

        if (cch < 15) {
            storeA(nxt);
            CP_WAIT0();
        }
        __syncthreads();
    }

    // epilogue
    const float* bb = (which == 0) ? bq : (which == 1) ? bk : bv;
    if (isv) {
#pragma unroll
        for (int im = 0; im < 2; im++)
#pragma unroll
            for (int jn = 0; jn < 8; jn++) {
                int rg  = m0 + warp_m * 32 + im * 16 + (lane >> 2);
                int col = warp_n * 64 + jn * 8 + (lane & 3) * 2;
                float b0 = bb[col], b1 = bb[col + 1];
                float* cc = c[im][jn];
                *(uint32_t*)&g_vh[(size_t)rg * DH + col] =
                    pkh2f(cc[0] + b0, cc[1] + b1);
                *(uint32_t*)&g_vh[(size_t)(rg + 8) * DH + col] =
                    pkh2f(cc[2] + b0, cc[3] + b1);
            }
    } else {
        __nv_bfloat16* __restrict__ oh = &g_h[which][0];
        __nv_bfloat16* __restrict__ ol = &g_l[which][0];
#pragma unroll
        for (int im = 0; im < 2; im++)
#pragma unroll
            for (int jn = 0; jn < 8; jn++) {
                int rg  = m0 + warp_m * 32 + im * 16 + (lane >> 2);
                int col = warp_n * 64 + jn * 8 + (lane & 3) * 2;
                float b0 = bb[col], b1 = bb[col + 1];
                float* cc = c[im][jn];
                float v0 = cc[0] + b0, v1 = cc[1] + b1;
                float v2 = cc[2] + b0, v3 = cc[3] + b1;
                __nv_bfloat16 h0 = __float2bfloat16(v0), h1 = __float2bfloat16(v1);
                __nv_bfloat16 h2 = __float2bfloat16(v2), h3 = __float2bfloat16(v3);
                *(uint32_t*)&oh[(size_t)rg * DH + col] = pk(h0, h1);
                *(uint32_t*)&ol[(size_t)rg * DH + col] =
                    pk(__float2bfloat16(v0 - __bfloat162float(h0)),
                       __float2bfloat16(v1 - __bfloat162float(h1)));
                *(uint32_t*)&oh[(size_t)(rg + 8) * DH + col] = pk(h2, h3);
                *(uint32_t*)&ol[(size_t)(rg + 8) * DH + col] =
                    pk(__float2bfloat16(v2 - __bfloat162float(h2)),
                       __float2bfloat16(v3 - __bfloat162float(h3)));
            }
    }
}

// ---------------------------------------------------------------------------
// Tensor-core flash attention, 2 CTAs/SM. Br=64, Bc=64, 128 threads (4 warps).
// Single-buffered KV (cross-CTA concurrency hides latency).
// QK^T: split-bf16 3-pass. PV: fp16 1-pass. exp2-domain softmax.
// ---------------------------------------------------------------------------
#define ROWB   272u                 // 136 halves padded row
#define QB64   (64u * ROWB)         // 17408 per Q split
#define KVT    (64u * ROWB)         // 17408 per array
#define KVBUF  (3u * KVT)           // Kh,Kl,Vh = 52224
#define AT_SMEM (2u * QB64 + KVBUF) // 87040 -> 2 CTAs/SM

__global__ __launch_bounds__(128, 2)
void attn_mma_kernel(float* __restrict__ out)
{
    const uint32_t sb = smem_u32(smdyn);
    const uint32_t Qh = sb;
    const uint32_t Ql = sb + QB64;
    const uint32_t KV = sb + 2 * QB64;

    const int bid = blockIdx.x;
    const int b    = bid & 15;
    const int tile = 31 - (bid >> 4);    // big tiles first
    const int q0   = tile * 64;
    const int tid  = threadIdx.x;
    const int wm   = tid >> 5;           // 0..3, warp owns rows wm*16..+15
    const int lane = tid & 31;

    const size_t bb = (size_t)b * SEQ * DH;
    const __nv_bfloat16* __restrict__ qh = &g_h[0][bb];
    const __nv_bfloat16* __restrict__ ql = &g_l[0][bb];
    const __nv_bfloat16* __restrict__ kh = &g_h[1][bb];
    const __nv_bfloat16* __restrict__ kl = &g_l[1][bb];
    const __nv_bfloat16* __restrict__ vh = (const __nv_bfloat16*)&g_vh[bb];

    // ---- preload Q (both splits): 2 arrays x 64 rows x 16 float4 ----
#pragma unroll
    for (int i = 0; i < 16; i++) {
        int f = tid + i * 128;           // 0..2047
        int arr = f >> 10;
        int e = f & 1023;
        int row = e >> 4, cc = e & 15;
        cpa16((arr ? Ql : Qh) + row * ROWB + cc * 16,
              (arr ? ql : qh) + (size_t)(q0 + row) * DH + cc * 8);
    }
    CP_COMMIT();

    float o[16][4];
#pragma unroll
    for (int t = 0; t < 16; t++)
#pragma unroll
        for (int q = 0; q < 4; q++) o[t][q] = 0.f;
    float m0r = -1e30f, m1r = -1e30f, l0r = 0.f, l1r = 0.f;

    const int r0 = q0 + wm * 16 + (lane >> 2);
    const int r1 = r0 + 8;

    const uint32_t aoff  = Qh + (uint32_t)((wm * 16 + (lane & 15)) * ROWB + (lane >> 4) * 16);
    const uint32_t aoffL = aoff + QB64;
    const uint32_t boffK = (uint32_t)(((lane & 7) + ((lane >> 4) << 3)) * ROWB +
                                      ((lane >> 3) & 1) * 16);
    const uint32_t boffV = (uint32_t)((lane & 15) * ROWB + (lane >> 4) * 16);

    const int nT = tile + 1;
    for (int t = 0; t < nT; t++) {
        const int kv0 = t * 64;

        // ---- load K/V chunk into (single) KV buffer ----
        // 3 arrays x 64 rows x 16 float4 = 3072 cpa16 / 128 thr = 24
#pragma unroll
        for (int i = 0; i < 24; i++) {
            int f = tid + i * 128;       // 0..3071
            int sel = f >> 10;
            int e = f & 1023;
            int row = e >> 4, cc = e & 15;
            const __nv_bfloat16* s = (sel == 0) ? kh : (sel == 1) ? kl : vh;
            cpa16(KV + sel * KVT + row * ROWB + cc * 16,
                  s + (size_t)(kv0 + row) * DH + cc * 8);
        }
        CP_COMMIT();
        CP_WAIT0();
        __syncthreads();

        // ---- S = Q K^T (split-bf16 3-pass) ----
        float s[8][4];
#pragma unroll
        for (int i = 0; i < 8; i++)
#pragma unroll
            for (int q = 0; q < 4; q++) s[i][q] = 0.f;

#pragma unroll
        for (int k16 = 0; k16 < 8; k16++) {
            uint32_t ah[4], al[4];
            ldsm4(ah, aoff  + k16 * 32);
            ldsm4(al, aoffL + k16 * 32);
#pragma unroll
            for (int n16 = 0; n16 < 4; n16++) {
                uint32_t bh[4], bl[4];
                ldsm4(bh, KV + 0 * KVT + boffK + n16 * (16 * ROWB) + k16 * 32);
                ldsm4(bl, KV + 1 * KVT + boffK + n16 * (16 * ROWB) + k16 * 32);
                mma_bf16(s[2 * n16 + 0], ah, bh[0], bh[1]);
                mma_bf16(s[2 * n16 + 1], ah, bh[2], bh[3]);
                mma_bf16(s[2 * n16 + 0], ah, bl[0], bl[1]);
                mma_bf16(s[2 * n16 + 1], ah, bl[2], bl[3]);
                mma_bf16(s[2 * n16 + 0], al, bh[0], bh[1]);
                mma_bf16(s[2 * n16 + 1], al, bh[2], bh[3]);
            }
        }

        // ---- scale (log2e folded), mask, online softmax (exp2 domain) ----
        const bool need_mask = (kv0 + 63) > (q0 + wm * 16);
#pragma unroll
        for (int ti = 0; ti < 8; ti++) {
            int colb = kv0 + ti * 8 + (lane & 3) * 2;
            if (need_mask) {
                s[ti][0] = (colb     <= r0) ? s[ti][0] * SCL : -1e30f;
                s[ti][1] = (colb + 1 <= r0) ? s[ti][1] * SCL : -1e30f;
                s[ti][2] = (colb     <= r1) ? s[ti][2] * SCL : -1e30f;
                s[ti][3] = (colb + 1 <= r1) ? s[ti][3] * SCL : -1e30f;
            } else {
                s[ti][0] *= SCL; s[ti][1] *= SCL;
                s[ti][2] *= SCL; s[ti][3] *= SCL;
            }
        }
        float mx0 = -1e30f, mx1 = -1e30f;
#pragma unroll
        for (int ti = 0; ti < 8; ti++) {
            mx0 = fmaxf(mx0, fmaxf(s[ti][0], s[ti][1]));
            mx1 = fmaxf(mx1, fmaxf(s[ti][2], s[ti][3]));
        }
        mx0 = fmaxf(mx0, __shfl_xor_sync(0xffffffffu, mx0, 1));
        mx0 = fmaxf(mx0, __shfl_xor_sync(0xffffffffu, mx0, 2));
        mx1 = fmaxf(mx1, __shfl_xor_sync(0xffffffffu, mx1, 1));
        mx1 = fmaxf(mx1, __shfl_xor_sync(0xffffffffu, mx1, 2));
        float mn0 = fmaxf(m0r, mx0), mn1 = fmaxf(m1r, mx1);
        float c0 = fexp2(m0r - mn0), c1 = fexp2(m1r - mn1);
        m0r = mn0; m1r = mn1;
        float ps0 = 0.f, ps1 = 0.f;
#pragma unroll
        for (int ti = 0; ti < 8; ti++) {
            s[ti][0] = fexp2(s[ti][0] - mn0);
            s[ti][1] = fexp2(s[ti][1] - mn0);
            s[ti][2] = fexp2(s[ti][2] - mn1);
            s[ti][3] = fexp2(s[ti][3] - mn1);
            ps0 += s[ti][0] + s[ti][1];
            ps1 += s[ti][2] + s[ti][3];
        }
        ps0 += __shfl_xor_sync(0xffffffffu, ps0, 1);
        ps0 += __shfl_xor_sync(0xffffffffu, ps0, 2);
        ps1 += __shfl_xor_sync(0xffffffffu, ps1, 1);
        ps1 += __shfl_xor_sync(0xffffffffu, ps1, 2);
        l0r = l0r * c0 + ps0;
        l1r = l1r * c1 + ps1;
#pragma unroll
        for (int ti = 0; ti < 16; ti++) {
            o[ti][0] *= c0; o[ti][1] *= c0;
            o[ti][2] *= c1; o[ti][3] *= c1;
        }

        // ---- P -> fp16 A fragments (packed cvt) ----
        uint32_t ph[4][4];
#pragma unroll
        for (int kbq = 0; kbq < 4; kbq++) {
            const int ta = 2 * kbq, tb = 2 * kbq + 1;
            ph[kbq][0] = pkh2f(s[ta][0], s[ta][1]);
            ph[kbq][1] = pkh2f(s[ta][2], s[ta][3]);
            ph[kbq][2] = pkh2f(s[tb][0], s[tb][1]);
            ph[kbq][3] = pkh2f(s[tb][2], s[tb][3]);
        }

        // ---- O += P V (fp16 1-pass), V via ldmatrix.trans ----
#pragma unroll
        for (int n16 = 0; n16 < 8; n16++) {
#pragma unroll
            for (int kbq = 0; kbq < 4; kbq++) {
                uint32_t bh[4];
                uint32_t va = KV + 2 * KVT + boffV +
                              (uint32_t)(kbq * 16 * ROWB + n16 * 32);
                ldsm4t(bh, va);
                mma_f16(o[2 * n16 + 0], ph[kbq], bh[0], bh[1]);
                mma_f16(o[2 * n16 + 1], ph[kbq], bh[2], bh[3]);
            }
        }

        __syncthreads();   // compute done before next chunk overwrites KV
    }

    // ---- epilogue ----
    const float i0 = 1.0f / l0r, i1 = 1.0f / l1r;
    const size_t ob0 = ((size_t)b * SEQ + r0) * DH;
    const size_t ob1 = ((size_t)b * SEQ + r1) * DH;
#pragma unroll
    for (int ti = 0; ti < 16; ti++) {
        int col = ti * 8 + (lane & 3) * 2;
        *(float2*)&out[ob0 + col] = make_float2(o[ti][0] * i0, o[ti][1] * i0);
        *(float2*)&out[ob1 + col] = make_float2(o[ti][2] * i1, o[ti][3] * i1);
    }
}

// ---------------------------------------------------------------------------
extern "C" void kernel_launch(void* const* d_in, const int* in_sizes, int n_in,
                              void* d_out, int out_size)
{
    const float* x  = (const float*)d_in[0];
    const float* Wq = (const float*)d_in[1];
    const float* bq = (const float*)d_in[2];
    const float* Wk = (const float*)d_in[3];
    const float* bk = (const float*)d_in[4];
    const float* Wv = (const float*)d_in[5];
    const float* bv = (const float*)d_in[6];
    float* out = (float*)d_out;

    wconv_kernel<<<1536, 256>>>(Wq, Wk, Wv);

    cudaFuncSetAttribute(proj_mma_kernel,
                         cudaFuncAttributeMaxDynamicSharedMemorySize, PJ_SMEM);
    dim3 gp(256, 3);
    proj_mma_kernel<<<gp, 256, PJ_SMEM>>>(x, bq, bk, bv);

    cudaFuncSetAttribute(attn_mma_kernel,
                         cudaFuncAttributeMaxDynamicSharedMemorySize, AT_SMEM);
    attn_mma_kernel<<<512, 128, AT_SMEM>>>(out);
}

// round 17
// speedup vs baseline: 1.0327x; 1.0327x over previous
#include <cuda_runtime.h>
#include <cuda_bf16.h>
#include <cuda_fp16.h>
#include <cstdint>

#define BATCH 16
#define SEQ   2048
#define EMB   1024
#define DH    128

// q,k split-bf16, natural [b][s][d]: index 0=q, 1=k
static __device__ __align__(16) __nv_bfloat16 g_h[2][(size_t)BATCH * SEQ * DH];
static __device__ __align__(16) __nv_bfloat16 g_l[2][(size_t)BATCH * SEQ * DH];
// v single fp16, natural [b][s][d]
static __device__ __align__(16) __half g_vh[(size_t)BATCH * SEQ * DH];
// Split-bf16 weights for q,k, B-operand layout [which][n][k]
static __device__ __align__(16) __nv_bfloat16 g_whi[2][DH][EMB];
static __device__ __align__(16) __nv_bfloat16 g_wlo[2][DH][EMB];
// fp16 weight for v
static __device__ __align__(16) __half g_wvh[DH][EMB];

extern __shared__ char smdyn[];

// ---------------------------------------------------------------------------
__device__ __forceinline__ uint32_t smem_u32(const void* p) {
    uint32_t a;
    asm("{ .reg .u64 t; cvta.to.shared.u64 t, %1; cvt.u32.u64 %0, t; }"
        : "=r"(a) : "l"(p));
    return a;
}
__device__ __forceinline__ void ldsm4(uint32_t* r, uint32_t addr) {
    asm volatile("ldmatrix.sync.aligned.m8n8.x4.shared.b16 {%0,%1,%2,%3}, [%4];"
                 : "=r"(r[0]), "=r"(r[1]), "=r"(r[2]), "=r"(r[3]) : "r"(addr));
}
__device__ __forceinline__ void ldsm4t(uint32_t* r, uint32_t addr) {
    asm volatile("ldmatrix.sync.aligned.m8n8.x4.trans.shared.b16 {%0,%1,%2,%3}, [%4];"
                 : "=r"(r[0]), "=r"(r[1]), "=r"(r[2]), "=r"(r[3]) : "r"(addr));
}
__device__ __forceinline__ void mma_bf16(float* c, const uint32_t* a,
                                         uint32_t b0, uint32_t b1) {
    asm volatile(
        "mma.sync.aligned.m16n8k16.row.col.f32.bf16.bf16.f32 "
        "{%0,%1,%2,%3}, {%4,%5,%6,%7}, {%8,%9}, {%0,%1,%2,%3};"
        : "+f"(c[0]), "+f"(c[1]), "+f"(c[2]), "+f"(c[3])
        : "r"(a[0]), "r"(a[1]), "r"(a[2]), "r"(a[3]), "r"(b0), "r"(b1));
}
__device__ __forceinline__ void mma_f16(float* c, const uint32_t* a,
                                        uint32_t b0, uint32_t b1) {
    asm volatile(
        "mma.sync.aligned.m16n8k16.row.col.f32.f16.f16.f32 "
        "{%0,%1,%2,%3}, {%4,%5,%6,%7}, {%8,%9}, {%0,%1,%2,%3};"
        : "+f"(c[0]), "+f"(c[1]), "+f"(c[2]), "+f"(c[3])
        : "r"(a[0]), "r"(a[1]), "r"(a[2]), "r"(a[3]), "r"(b0), "r"(b1));
}
__device__ __forceinline__ uint32_t pk(__nv_bfloat16 a, __nv_bfloat16 b) {
    __nv_bfloat162 t = __halves2bfloat162(a, b);
    return *(uint32_t*)&t;
}
__device__ __forceinline__ uint32_t pkh(__half a, __half b) {
    __half2 t = __halves2half2(a, b);
    return *(uint32_t*)&t;
}
__device__ __forceinline__ uint32_t pkh2f(float a, float b) {
    uint32_t r;
    asm("cvt.rn.f16x2.f32 %0, %2, %1;" : "=r"(r) : "f"(a), "f"(b));
    return r;
}
__device__ __forceinline__ void cpa16(uint32_t dst, const void* src) {
    asm volatile("cp.async.cg.shared.global [%0], [%1], 16;"
                 :: "r"(dst), "l"(src) : "memory");
}
#define CP_COMMIT() asm volatile("cp.async.commit_group;" ::: "memory")
#define CP_WAIT0()  asm volatile("cp.async.wait_group 0;" ::: "memory")

__device__ __forceinline__ float fexp2(float x) {
    float r;
    asm("ex2.approx.f32 %0, %1;" : "=f"(r) : "f"(x));
    return r;
}

// log2(e) * 32 (score scale folded with exp->exp2 conversion)
#define SCL 46.166241308446828f

// ---------------------------------------------------------------------------
// Convert weights via smem transpose tile: coalesced loads AND stores.
// grid 384: which(3) x ktile(32) x ntile(4); block 256 (32x8).
// ---------------------------------------------------------------------------
__global__ __launch_bounds__(256)
void wconv_kernel(const float* __restrict__ Wq,
                  const float* __restrict__ Wk,
                  const float* __restrict__ Wv)
{
    __shared__ float t[32][33];
    const int blk   = blockIdx.x;
    const int which = blk >> 7;          // 128 blocks per which
    const int r     = blk & 127;
    const int k0    = (r >> 2) * 32;     // 32 k-tiles
    const int n0    = (r & 3) * 32;      // 4 n-tiles
    const int tx = threadIdx.x & 31;
    const int ty = threadIdx.x >> 5;

    const float* __restrict__ W = (which == 0) ? Wq : (which == 1) ? Wk : Wv;

#pragma unroll
    for (int i = 0; i < 4; i++)
        t[ty + 8 * i][tx] = W[(size_t)(k0 + ty + 8 * i) * DH + n0 + tx];
    __syncthreads();

#pragma unroll
    for (int i = 0; i < 4; i++) {
        int n = n0 + ty + 8 * i;
        int k = k0 + tx;
        float x = t[tx][ty + 8 * i];
        if (which == 2) {
            g_wvh[n][k] = __float2half_rn(x);
        } else {
            __nv_bfloat16 hi = __float2bfloat16(x);
            __nv_bfloat16 lo = __float2bfloat16(x - __bfloat162float(hi));
            g_whi[which][n][k] = hi;
            g_wlo[which][n][k] = lo;
        }
    }
}

// ---------------------------------------------------------------------------
// mma.sync projection, BK=64, double-buffered smem + cp.async B path.
// q,k: split-bf16 3-pass. v: fp16 1-pass.
// BM=128, BN=128, BK=64; 8 warps in 4x2; warp tile 32x64.
// Row stride 144 B -> conflict-free ldmatrix.
// ---------------------------------------------------------------------------
#define PJ_T      18432u          // one array: 128 rows * 144 B
#define PJ_STAGE  (4u * PJ_T)     // A_hi, A_lo, B_hi, B_lo = 73728
#define PJ_SMEM   (2u * PJ_STAGE) // 147456

__global__ __launch_bounds__(256)
void proj_mma_kernel(const float* __restrict__ X,
                     const float* __restrict__ bq,
                     const float* __restrict__ bk,
                     const float* __restrict__ bv)
{
    const uint32_t sb = smem_u32(smdyn);

    const int which = blockIdx.y;
    const bool isv  = (which == 2);
    const int m0    = blockIdx.x * 128;
    const int tid   = threadIdx.x;
    const int wid   = tid >> 5;
    const int lane  = tid & 31;
    const int warp_m = wid >> 1;
    const int warp_n = wid & 1;

    const __nv_bfloat16* __restrict__ whi =
        isv ? (const __nv_bfloat16*)&g_wvh[0][0] : &g_whi[which][0][0];
    const __nv_bfloat16* __restrict__ wlo =
        isv ? (const __nv_bfloat16*)&g_wvh[0][0] : &g_wlo[which][0][0];

    float c[2][8][4];
#pragma unroll
    for (int i = 0; i < 2; i++)
#pragma unroll
        for (int j = 0; j < 8; j++)
#pragma unroll
            for (int q = 0; q < 4; q++) c[i][j][q] = 0.f;

    const uint32_t a_off =
        (uint32_t)((warp_m * 32 + (lane & 15)) * 144 + (lane >> 4) * 16);
    const uint32_t b_off =
        (uint32_t)((warp_n * 64 + (lane & 7) + ((lane >> 4) << 3)) * 144 +
                   ((lane >> 3) & 1) * 16);

    float4 ra[8];

    auto cpasyncB = [&](uint32_t stage, int k0) {
#pragma unroll
        for (int i = 0; i < 4; i++) {
            int f = tid + i * 256;
            int n = f >> 3, k8 = f & 7;
            uint32_t off = (uint32_t)(n * 144 + k8 * 16);
            cpa16(stage + 2 * PJ_T + off, whi + (size_t)n * EMB + k0 + k8 * 8);
            if (!isv)
                cpa16(stage + 3 * PJ_T + off, wlo + (size_t)n * EMB + k0 + k8 * 8);
        }
    };
    auto loadA = [&](int k0) {
#pragma unroll
        for (int i = 0; i < 8; i++) {
            int f = tid + i * 256;
            int row = f >> 4, k4 = f & 15;
            ra[i] = *(const float4*)&X[(size_t)(m0 + row) * EMB + k0 + k4 * 4];
        }
    };
    auto storeA = [&](uint32_t stage) {
#pragma unroll
        for (int i = 0; i < 8; i++) {
            int f = tid + i * 256;
            int row = f >> 4, k4 = f & 15;
            float4 v = ra[i];
            uint32_t off = (uint32_t)(row * 144 + k4 * 8);
            if (isv) {
                uint64_t hv = (uint64_t)pkh(__float2half_rn(v.x), __float2half_rn(v.y))
                            | ((uint64_t)pkh(__float2half_rn(v.z), __float2half_rn(v.w)) << 32);
                asm volatile("st.shared.b64 [%0], %1;" :: "r"(stage + off), "l"(hv) : "memory");
            } else {
                __nv_bfloat16 h0 = __float2bfloat16(v.x);
                __nv_bfloat16 h1 = __float2bfloat16(v.y);
                __nv_bfloat16 h2 = __float2bfloat16(v.z);
                __nv_bfloat16 h3 = __float2bfloat16(v.w);
                __nv_bfloat16 l0 = __float2bfloat16(v.x - __bfloat162float(h0));
                __nv_bfloat16 l1 = __float2bfloat16(v.y - __bfloat162float(h1));
                __nv_bfloat16 l2 = __float2bfloat16(v.z - __bfloat162float(h2));
                __nv_bfloat16 l3 = __float2bfloat16(v.w - __bfloat162float(h3));
                uint64_t hv = (uint64_t)pk(h0, h1) | ((uint64_t)pk(h2, h3) << 32);
                uint64_t lv = (uint64_t)pk(l0, l1) | ((uint64_t)pk(l2, l3) << 32);
                asm volatile("st.shared.b64 [%0], %1;" :: "r"(stage + off), "l"(hv) : "memory");
                asm volatile("st.shared.b64 [%0], %1;" :: "r"(stage + PJ_T + off), "l"(lv) : "memory");
            }
        }
    };

    cpasyncB(sb, 0);
    CP_COMMIT();
    loadA(0);
    storeA(sb);
    CP_WAIT0();
    __syncthreads();

    for (int cch = 0; cch < 16; cch++) {
        const uint32_t cur = sb + (uint32_t)(cch & 1) * PJ_STAGE;
        const uint32_t nxt = sb + (uint32_t)((cch + 1) & 1) * PJ_STAGE;

        if (cch < 15) {
            cpasyncB(nxt, (cch + 1) * 64);
            CP_COMMIT();
            loadA((cch + 1) * 64);
        }

#pragma unroll
        for (int ks = 0; ks < 4; ks++) {
            uint32_t ah[2][4], al[2][4], bh[4][4], bl[4][4];
#pragma unroll
            for (int im = 0; im < 2; im++) {
                ldsm4(ah[im], cur + a_off + im * 2304 + ks * 32);
                if (!isv) ldsm4(al[im], cur + PJ_T + a_off + im * 2304 + ks * 32);
            }
#pragma unroll
            for (int jn2 = 0; jn2 < 4; jn2++) {
                ldsm4(bh[jn2], cur + 2 * PJ_T + b_off + jn2 * 2304 + ks * 32);
                if (!isv) ldsm4(bl[jn2], cur + 3 * PJ_T + b_off + jn2 * 2304 + ks * 32);
            }
            if (isv) {
#pragma unroll
                for (int im = 0; im < 2; im++)
#pragma unroll
                    for (int jn2 = 0; jn2 < 4; jn2++) {
                        mma_f16(c[im][jn2 * 2 + 0], ah[im], bh[jn2][0], bh[jn2][1]);
                        mma_f16(c[im][jn2 * 2 + 1], ah[im], bh[jn2][2], bh[jn2][3]);
                    }
            } else {
#pragma unroll
                for (int im = 0; im < 2; im++)
#pragma unroll
                    for (int jn2 = 0; jn2 < 4; jn2++) {
                        mma_bf16(c[im][jn2 * 2 + 0], ah[im], bh[jn2][0], bh[jn2][1]);
                        mma_bf16(c[im][jn2 * 2 + 1], ah[im], bh[jn2][2], bh[jn2][3]);
                        mma_bf16(c[im][jn2 * 2 + 0], ah[im], bl[jn2][0], bl[jn2][1]);
                        mma_bf16(c[im][jn2 * 2 + 1], ah[im], bl[jn2][2], bl[jn2][3]);
                        mma_bf16(c[im][jn2 * 2 + 0], al[im], bh[jn2][0], bh[jn2][1]);
                        mma_bf16(c[im][jn2 * 2 + 1], al[im], bh[jn2][2], bh[jn2][3]);
                    }
            }
        }

        if (cch < 15) {
            storeA(nxt);
            CP_WAIT0();
        }
        __syncthreads();
    }

    // epilogue
    const float* bb = (which == 0) ? bq : (which == 1) ? bk : bv;
    if (isv) {
#pragma unroll
        for (int im = 0; im < 2; im++)
#pragma unroll
            for (int jn = 0; jn < 8; jn++) {
                int rg  = m0 + warp_m * 32 + im * 16 + (lane >> 2);
                int col = warp_n * 64 + jn * 8 + (lane & 3) * 2;
                float b0 = bb[col], b1 = bb[col + 1];
                float* cc = c[im][jn];
                *(uint32_t*)&g_vh[(size_t)rg * DH + col] =
                    pkh2f(cc[0] + b0, cc[1] + b1);
                *(uint32_t*)&g_vh[(size_t)(rg + 8) * DH + col] =
                    pkh2f(cc[2] + b0, cc[3] + b1);
            }
    } else {
        __nv_bfloat16* __restrict__ oh = &g_h[which][0];
        __nv_bfloat16* __restrict__ ol = &g_l[which][0];
#pragma unroll
        for (int im = 0; im < 2; im++)
#pragma unroll
            for (int jn = 0; jn < 8; jn++) {
                int rg  = m0 + warp_m * 32 + im * 16 + (lane >> 2);
                int col = warp_n * 64 + jn * 8 + (lane & 3) * 2;
                float b0 = bb[col], b1 = bb[col + 1];
                float* cc = c[im][jn];
                float v0 = cc[0] + b0, v1 = cc[1] + b1;
                float v2 = cc[2] + b0, v3 = cc[3] + b1;
                __nv_bfloat16 h0 = __float2bfloat16(v0), h1 = __float2bfloat16(v1);
                __nv_bfloat16 h2 = __float2bfloat16(v2), h3 = __float2bfloat16(v3);
                *(uint32_t*)&oh[(size_t)rg * DH + col] = pk(h0, h1);
                *(uint32_t*)&ol[(size_t)rg * DH + col] =
                    pk(__float2bfloat16(v0 - __bfloat162float(h0)),
                       __float2bfloat16(v1 - __bfloat162float(h1)));
                *(uint32_t*)&oh[(size_t)(rg + 8) * DH + col] = pk(h2, h3);
                *(uint32_t*)&ol[(size_t)(rg + 8) * DH + col] =
                    pk(__float2bfloat16(v2 - __bfloat162float(h2)),
                       __float2bfloat16(v3 - __bfloat162float(h3)));
            }
    }
}

// ---------------------------------------------------------------------------
// Tensor-core flash attention (R15). Br=128, Bc=64, 8 warps, double-buffered.
// QK^T: split-bf16 3-pass. PV: fp16 1-pass. exp2-domain softmax.
// ---------------------------------------------------------------------------
#define ROWB   272u                 // 136 halves padded row
#define QBYT   (128u * ROWB)        // 34816 per split
#define KVT    (64u * ROWB)         // 17408 per array
#define KVBUF  (3u * KVT)           // Kh,Kl,Vh = 52224
#define AT_SMEM (2u * QBYT + 2u * KVBUF)   // 174080

__global__ __launch_bounds__(256, 1)
void attn_mma_kernel(float* __restrict__ out)
{
    const uint32_t sb = smem_u32(smdyn);
    const uint32_t Qh = sb;
    const uint32_t Ql = sb + QBYT;
    const uint32_t KV = sb + 2 * QBYT;   // + buf*KVBUF + sel*KVT

    const int bid = blockIdx.x;
    const int b   = bid & 15;
    const int qt  = 15 - (bid >> 4);     // big tiles first
    const int q0  = qt * 128;
    const int tid = threadIdx.x;
    const int wm  = tid >> 5;
    const int lane = tid & 31;

    const size_t bb = (size_t)b * SEQ * DH;
    const __nv_bfloat16* __restrict__ qh = &g_h[0][bb];
    const __nv_bfloat16* __restrict__ ql = &g_l[0][bb];
    const __nv_bfloat16* __restrict__ kh = &g_h[1][bb];
    const __nv_bfloat16* __restrict__ kl = &g_l[1][bb];
    const __nv_bfloat16* __restrict__ vh = (const __nv_bfloat16*)&g_vh[bb];

    // ---- preload Q (both splits) + chunk 0 of K/V ----
#pragma unroll
    for (int i = 0; i < 16; i++) {
        int f = tid + i * 256;
        int arr = f >> 11;
        int e = f & 2047;
        int row = e >> 4, cc = e & 15;
        cpa16((arr ? Ql : Qh) + row * ROWB + cc * 16,
              (arr ? ql : qh) + (size_t)(q0 + row) * DH + cc * 8);
    }
    const int nT = 2 * qt + 2;
    {
#pragma unroll
        for (int i = 0; i < 12; i++) {
            int f = tid + i * 256;
            int sel = f >> 10;
            int e = f & 1023;
            int row = e >> 4, cc = e & 15;
            const __nv_bfloat16* s = (sel == 0) ? kh : (sel == 1) ? kl : vh;
            cpa16(KV + sel * KVT + row * ROWB + cc * 16,
                  s + (size_t)row * DH + cc * 8);
        }
    }
    CP_COMMIT();
    CP_WAIT0();
    __syncthreads();

    float o[16][4];
#pragma unroll
    for (int t = 0; t < 16; t++)
#pragma unroll
        for (int q = 0; q < 4; q++) o[t][q] = 0.f;
    float m0r = -1e30f, m1r = -1e30f, l0r = 0.f, l1r = 0.f;

    const int r0 = q0 + wm * 16 + (lane >> 2);
    const int r1 = r0 + 8;

    const uint32_t aoff  = Qh + (uint32_t)((wm * 16 + (lane & 15)) * ROWB + (lane >> 4) * 16);
    const uint32_t aoffL = aoff + (Ql - Qh);
    const uint32_t boffK = (uint32_t)(((lane & 7) + ((lane >> 4) << 3)) * ROWB +
                                      ((lane >> 3) & 1) * 16);
    const uint32_t boffV = (uint32_t)((lane & 15) * ROWB + (lane >> 4) * 16);

    for (int t = 0; t < nT; t++) {
        const int kv0 = t * 64;
        const uint32_t kb = KV + (uint32_t)(t & 1) * KVBUF;

        if (t + 1 < nT) {
            const int nkv = (t + 1) * 64;
            const uint32_t nb = KV + (uint32_t)((t + 1) & 1) * KVBUF;
#pragma unroll
            for (int i = 0; i < 12; i++) {
                int f = tid + i * 256;
                int sel = f >> 10;
                int e = f & 1023;
                int row = e >> 4, cc = e & 15;
                const __nv_bfloat16* s = (sel == 0) ? kh : (sel == 1) ? kl : vh;
                cpa16(nb + sel * KVT + row * ROWB + cc * 16,
                      s + (size_t)(nkv + row) * DH + cc * 8);
            }
            CP_COMMIT();
        }

        const bool active = kv0 <= (q0 + wm * 16 + 15);
        if (active) {
            // ---- S = Q K^T (split-bf16 3-pass) ----
            float s[8][4];
#pragma unroll
            for (int i = 0; i < 8; i++)
#pragma unroll
                for (int q = 0; q < 4; q++) s[i][q] = 0.f;

#pragma unroll
            for (int k16 = 0; k16 < 8; k16++) {
                uint32_t ah[4], al[4];
                ldsm4(ah, aoff  + k16 * 32);
                ldsm4(al, aoffL + k16 * 32);
#pragma unroll
                for (int n16 = 0; n16 < 4; n16++) {
                    uint32_t bh[4], bl[4];
                    ldsm4(bh, kb + 0 * KVT + boffK + n16 * (16 * ROWB) + k16 * 32);
                    ldsm4(bl, kb + 1 * KVT + boffK + n16 * (16 * ROWB) + k16 * 32);
                    mma_bf16(s[2 * n16 + 0], ah, bh[0], bh[1]);
                    mma_bf16(s[2 * n16 + 1], ah, bh[2], bh[3]);
                    mma_bf16(s[2 * n16 + 0], ah, bl[0], bl[1]);
                    mma_bf16(s[2 * n16 + 1], ah, bl[2], bl[3]);
                    mma_bf16(s[2 * n16 + 0], al, bh[0], bh[1]);
                    mma_bf16(s[2 * n16 + 1], al, bh[2], bh[3]);
                }
            }

            // ---- scale (log2e folded), mask, online softmax (exp2 domain) ----
            const bool need_mask = (kv0 + 63) > (q0 + wm * 16);
#pragma unroll
            for (int ti = 0; ti < 8; ti++) {
                int colb = kv0 + ti * 8 + (lane & 3) * 2;
                if (need_mask) {
                    s[ti][0] = (colb     <= r0) ? s[ti][0] * SCL : -1e30f;
                    s[ti][1] = (colb + 1 <= r0) ? s[ti][1] * SCL : -1e30f;
                    s[ti][2] = (colb     <= r1) ? s[ti][2] * SCL : -1e30f;
                    s[ti][3] = (colb + 1 <= r1) ? s[ti][3] * SCL : -1e30f;
                } else {
                    s[ti][0] *= SCL; s[ti][1] *= SCL;
                    s[ti][2] *= SCL; s[ti][3] *= SCL;
                }
            }
            float mx0 = -1e30f, mx1 = -1e30f;
#pragma unroll
            for (int ti = 0; ti < 8; ti++) {
                mx0 = fmaxf(mx0, fmaxf(s[ti][0], s[ti][1]));
                mx1 = fmaxf(mx1, fmaxf(s[ti][2], s[ti][3]));
            }
            mx0 = fmaxf(mx0, __shfl_xor_sync(0xffffffffu, mx0, 1));
            mx0 = fmaxf(mx0, __shfl_xor_sync(0xffffffffu, mx0, 2));
            mx1 = fmaxf(mx1, __shfl_xor_sync(0xffffffffu, mx1, 1));
            mx1 = fmaxf(mx1, __shfl_xor_sync(0xffffffffu, mx1, 2));
            float mn0 = fmaxf(m0r, mx0), mn1 = fmaxf(m1r, mx1);
            float c0 = fexp2(m0r - mn0), c1 = fexp2(m1r - mn1);
            m0r = mn0; m1r = mn1;
            float ps0 = 0.f, ps1 = 0.f;
#pragma unroll
            for (int ti = 0; ti < 8; ti++) {
                s[ti][0] = fexp2(s[ti][0] - mn0);
                s[ti][1] = fexp2(s[ti][1] - mn0);
                s[ti][2] = fexp2(s[ti][2] - mn1);
                s[ti][3] = fexp2(s[ti][3] - mn1);
                ps0 += s[ti][0] + s[ti][1];
                ps1 += s[ti][2] + s[ti][3];
            }
            ps0 += __shfl_xor_sync(0xffffffffu, ps0, 1);
            ps0 += __shfl_xor_sync(0xffffffffu, ps0, 2);
            ps1 += __shfl_xor_sync(0xffffffffu, ps1, 1);
            ps1 += __shfl_xor_sync(0xffffffffu, ps1, 2);
            l0r = l0r * c0 + ps0;
            l1r = l1r * c1 + ps1;
#pragma unroll
            for (int ti = 0; ti < 16; ti++) {
                o[ti][0] *= c0; o[ti][1] *= c0;
                o[ti][2] *= c1; o[ti][3] *= c1;
            }

            // ---- P -> fp16 A fragments (packed cvt) ----
            uint32_t ph[4][4];
#pragma unroll
            for (int kbq = 0; kbq < 4; kbq++) {
                const int ta = 2 * kbq, tb = 2 * kbq + 1;
                ph[kbq][0] = pkh2f(s[ta][0], s[ta][1]);
                ph[kbq][1] = pkh2f(s[ta][2], s[ta][3]);
                ph[kbq][2] = pkh2f(s[tb][0], s[tb][1]);
                ph[kbq][3] = pkh2f(s[tb][2], s[tb][3]);
            }

            // ---- O += P V (fp16 1-pass), V via ldmatrix.trans ----
#pragma unroll
            for (int n16 = 0; n16 < 8; n16++) {
#pragma unroll
                for (int kbq = 0; kbq < 4; kbq++) {
                    uint32_t bh[4];
                    uint32_t va = kb + 2 * KVT + boffV +
                                  (uint32_t)(kbq * 16 * ROWB + n16 * 32);
                    ldsm4t(bh, va);
                    mma_f16(o[2 * n16 + 0], ph[kbq], bh[0], bh[1]);
                    mma_f16(o[2 * n16 + 1], ph[kbq], bh[2], bh[3]);
                }
            }
        }

        if (t + 1 < nT) CP_WAIT0();
        __syncthreads();
    }

    // ---- epilogue ----
    const float i0 = 1.0f / l0r, i1 = 1.0f / l1r;
    const size_t ob0 = ((size_t)b * SEQ + r0) * DH;
    const size_t ob1 = ((size_t)b * SEQ + r1) * DH;
#pragma unroll
    for (int ti = 0; ti < 16; ti++) {
        int col = ti * 8 + (lane & 3) * 2;
        *(float2*)&out[ob0 + col] = make_float2(o[ti][0] * i0, o[ti][1] * i0);
        *(float2*)&out[ob1 + col] = make_float2(o[ti][2] * i1, o[ti][3] * i1);
    }
}

// ---------------------------------------------------------------------------
extern "C" void kernel_launch(void* const* d_in, const int* in_sizes, int n_in,
                              void* d_out, int out_size)
{
    const float* x  = (const float*)d_in[0];
    const float* Wq = (const float*)d_in[1];
    const float* bq = (const float*)d_in[2];
    const float* Wk = (const float*)d_in[3];
    const float* bk = (const float*)d_in[4];
    const float* Wv = (const float*)d_in[5];
    const float* bv = (const float*)d_in[6];
    float* out = (float*)d_out;

    wconv_kernel<<<384, 256>>>(Wq, Wk, Wv);

    cudaFuncSetAttribute(proj_mma_kernel,
                         cudaFuncAttributeMaxDynamicSharedMemorySize, PJ_SMEM);
    dim3 gp(256, 3);
    proj_mma_kernel<<<gp, 256, PJ_SMEM>>>(x, bq, bk, bv);

    cudaFuncSetAttribute(attn_mma_kernel,
                         cudaFuncAttributeMaxDynamicSharedMemorySize, AT_SMEM);
    attn_mma_kernel<<<256, 256, AT_SMEM>>>(out);
}